// round 13
// baseline (speedup 1.0000x reference)
#include <cuda_runtime.h>
#include <cstdint>

// Problem constants
#define HW4     65536          // (512*512)/4 float4-groups per (b,c) plane
#define NGROUP  524288         // NPIX/4
#define NPIX    2097152
#define TPB     128
#define GPB     128            // groups per tile (== TPB, 1 group/thread)
#define NTILES  4096           // NGROUP / GPB
#define GRID    608            // 152 SMs x 4 resident blocks -> exact single wave
#define STAGES  2

#define SY_TILE_BYTES  (GPB * 36 * 4)     // 18432 B sigma_y per tile

__device__ float        g_psum[GRID];
__device__ float        g_pmax[GRID];
__device__ unsigned int g_count = 0;

__device__ __forceinline__ uint32_t smem_u32(const void* p) {
    uint32_t a;
    asm("{ .reg .u64 t; cvta.to.shared.u64 t, %1; cvt.u32.u64 %0, t; }" : "=r"(a) : "l"(p));
    return a;
}

__device__ __forceinline__ void tma_sigma(const float4* dst, const float* sy,
                                          unsigned tile, uint32_t mbar) {
    asm volatile("mbarrier.arrive.expect_tx.shared.b64 _, [%0], %1;"
                 :: "r"(mbar), "r"((uint32_t)SY_TILE_BYTES) : "memory");
    asm volatile(
        "cp.async.bulk.shared::cta.global.mbarrier::complete_tx::bytes "
        "[%0], [%1], %2, [%3];"
        :: "r"(smem_u32(dst)),
           "l"((const char*)sy + (size_t)tile * SY_TILE_BYTES),
           "r"((uint32_t)SY_TILE_BYTES), "r"(mbar) : "memory");
}

__device__ __forceinline__ void mbar_wait(uint32_t mbar, uint32_t parity) {
    uint32_t done;
    asm volatile(
        "{\n\t.reg .pred p;\n\t"
        "mbarrier.try_wait.parity.acquire.cta.shared::cta.b64 p, [%1], %2;\n\t"
        "selp.b32 %0, 1, 0, p;\n\t}"
        : "=r"(done) : "r"(mbar), "r"(parity) : "memory");
    while (!done) {
        asm volatile(
            "{\n\t.reg .pred p;\n\t"
            "mbarrier.try_wait.parity.acquire.cta.shared::cta.b64 p, [%1], %2, 0x989680;\n\t"
            "selp.b32 %0, 1, 0, p;\n\t}"
            : "=r"(done) : "r"(mbar), "r"(parity) : "memory");
    }
}

// load the 6 tg/mu float4s for a tile (issued early = software prefetch)
__device__ __forceinline__ void load_tm(const float4* __restrict__ tg,
                                        const float4* __restrict__ mu,
                                        unsigned tile, unsigned tid,
                                        float4& T0, float4& T1, float4& T2,
                                        float4& M0, float4& M1, float4& M2) {
    const unsigned g  = tile * GPB + tid;
    const unsigned b  = g >> 16;
    const unsigned tb = b * 3 * HW4 + (g & (HW4 - 1));
    T0 = tg[tb];           M0 = mu[tb];
    T1 = tg[tb + HW4];     M1 = mu[tb + HW4];
    T2 = tg[tb + 2 * HW4]; M2 = mu[tb + 2 * HW4];
}

__global__ __launch_bounds__(TPB, 4) void map_loss_fused(
    const float4* __restrict__ tg,
    const float4* __restrict__ mu,
    const float*  __restrict__ sy,
    float* __restrict__ out)
{
    __shared__ alignas(128) float4 s_sy[STAGES][GPB * 9];   // 2 x 18432 B
    __shared__ alignas(8)  uint64_t s_mbar[STAGES];

    const unsigned tid = threadIdx.x;
    const unsigned bid = blockIdx.x;
    const int ntile = (NTILES - (int)bid + GRID - 1) / GRID;   // 6 or 7

    if (tid == 0) {
        asm volatile("mbarrier.init.shared.b64 [%0], 1;" :: "r"(smem_u32(&s_mbar[0])) : "memory");
        asm volatile("mbarrier.init.shared.b64 [%0], 1;" :: "r"(smem_u32(&s_mbar[1])) : "memory");
    }
    __syncthreads();
    if (tid == 0) {
        tma_sigma(s_sy[0], sy, bid, smem_u32(&s_mbar[0]));
        if (ntile > 1)
            tma_sigma(s_sy[1], sy, bid + GRID, smem_u32(&s_mbar[1]));
    }

    // register prefetch of tg/mu for tile 0
    float4 cT0, cT1, cT2, cM0, cM1, cM2;
    load_tm(tg, mu, bid, tid, cT0, cT1, cT2, cM0, cM1, cM2);

    float lsum = 0.0f;
    float lmax = -3.0e38f;

    for (int k = 0; k < ntile; ++k) {
        const int      stage  = k & 1;
        const uint32_t parity = (k >> 1) & 1;

        // prefetch tg/mu for NEXT tile before blocking on this tile's sigma
        float4 nT0, nT1, nT2, nM0, nM1, nM2;
        if (k + 1 < ntile)
            load_tm(tg, mu, bid + (unsigned)(k + 1) * GRID, tid,
                    nT0, nT1, nT2, nM0, nM1, nM2);

        mbar_wait(smem_u32(&s_mbar[stage]), parity);

        // sigma -> registers, then free the buffer immediately
        float S[36];
        #pragma unroll
        for (int q = 0; q < 9; ++q) {
            const float4 v = s_sy[stage][tid * 9 + q];
            S[4 * q + 0] = v.x; S[4 * q + 1] = v.y;
            S[4 * q + 2] = v.z; S[4 * q + 3] = v.w;
        }
        __syncthreads();
        if (tid == 0 && k + STAGES < ntile)
            tma_sigma(s_sy[stage], sy, bid + (unsigned)(k + STAGES) * GRID,
                      smem_u32(&s_mbar[stage]));

        // ---- math ----
        const float r0[4] = {cT0.x - cM0.x, cT0.y - cM0.y, cT0.z - cM0.z, cT0.w - cM0.w};
        const float r1[4] = {cT1.x - cM1.x, cT1.y - cM1.y, cT1.z - cM1.z, cT1.w - cM1.w};
        const float r2[4] = {cT2.x - cM2.x, cT2.y - cM2.y, cT2.z - cM2.z, cT2.w - cM2.w};

        float quad[4], det[4];
        #pragma unroll
        for (int j = 0; j < 4; ++j) {
            const float a  = S[9 * j + 0];
            const float bb = S[9 * j + 1];
            const float c  = S[9 * j + 2];
            const float d  = S[9 * j + 4];
            const float e  = S[9 * j + 5];
            const float f  = S[9 * j + 8];
            const float A00 = d * f - e * e;
            const float A01 = c * e - bb * f;
            const float A02 = bb * e - c * d;
            const float A11 = a * f - c * c;
            const float A12 = bb * c - a * e;
            const float A22 = a * d - bb * bb;
            det[j] = a * A00 + bb * A01 + c * A02;
            quad[j] = r0[j] * r0[j] * A00 + r1[j] * r1[j] * A11 + r2[j] * r2[j] * A22
                    + 2.0f * (r0[j] * r1[j] * A01 + r0[j] * r2[j] * A02 + r1[j] * r2[j] * A12);
            // guard: t1 = 0.5*quad/det > 1e8  <=>  quad - 2e8*det > 0  (det > 0)
            lmax = fmaxf(lmax, quad[j] - 2.0e8f * det[j]);
        }

        const float d01 = det[0] * det[1];
        const float d23 = det[2] * det[3];
        const float num = (quad[0] * det[1] + quad[1] * det[0]) * d23
                        + (quad[2] * det[3] + quad[3] * det[2]) * d01;
        const float dp  = d01 * d23;            // dets >= 1, product <= ~1e13 : safe
        lsum += 0.5f * (__fdividef(num, dp) + __logf(dp));

        // rotate prefetched registers
        cT0 = nT0; cT1 = nT1; cT2 = nT2;
        cM0 = nM0; cM1 = nM1; cM2 = nM2;
    }

    // ---- intra-block reduction (4 warps) ----
    const int lane = tid & 31;
    const int wid  = tid >> 5;
    #pragma unroll
    for (int off = 16; off > 0; off >>= 1) {
        lsum += __shfl_down_sync(0xffffffffu, lsum, off);
        lmax  = fmaxf(lmax, __shfl_down_sync(0xffffffffu, lmax, off));
    }
    __shared__ float wsum[TPB / 32];
    __shared__ float wmax[TPB / 32];
    if (lane == 0) { wsum[wid] = lsum; wmax[wid] = lmax; }
    __syncthreads();
    __shared__ bool s_last;
    if (tid == 0) {
        float bs = wsum[0], bm = wmax[0];
        #pragma unroll
        for (int w = 1; w < TPB / 32; ++w) { bs += wsum[w]; bm = fmaxf(bm, wmax[w]); }
        g_psum[bid] = bs;
        g_pmax[bid] = bm;
        __threadfence();
        const unsigned done = atomicAdd(&g_count, 1u);
        s_last = (done == GRID - 1);
    }
    __syncthreads();

    // ---- last block finalizes (no second launch) — scalar gather (proven) ----
    if (s_last) {
        double ds = 0.0;
        float  dm = -3.0e38f;
        #pragma unroll
        for (int k = 0; k < (GRID + TPB - 1) / TPB; ++k) {
            const int idx = tid + k * TPB;
            if (idx < GRID) {
                ds += (double)g_psum[idx];
                dm  = fmaxf(dm, g_pmax[idx]);
            }
        }
        __shared__ double fsum[TPB];
        __shared__ float  fmaxv[TPB];
        fsum[tid]  = ds;
        fmaxv[tid] = dm;
        __syncthreads();
        #pragma unroll
        for (int off = TPB / 2; off > 0; off >>= 1) {
            if (tid < off) {
                fsum[tid] += fsum[tid + off];
                fmaxv[tid] = fmaxf(fmaxv[tid], fmaxv[tid + off]);
            }
            __syncthreads();
        }
        if (tid == 0) {
            float loss = (float)(fsum[0] / (double)NPIX);
            if (fmaxv[0] > 0.0f) loss = 0.0f;   // max(t1) > 1e8 guard
            out[0] = loss;
            g_count = 0;                         // reset for next graph replay
        }
    }
}

extern "C" void kernel_launch(void* const* d_in, const int* in_sizes, int n_in,
                              void* d_out, int out_size)
{
    // metadata order: target, mu, sigma_mu, sigma_n, sigma_y
    const float4* target = (const float4*)d_in[0];
    const float4* mu     = (const float4*)d_in[1];
    const float*  sy     = (const float*)d_in[4];
    float* out = (float*)d_out;

    map_loss_fused<<<GRID, TPB>>>(target, mu, sy, out);
}

// round 14
// speedup vs baseline: 1.0447x; 1.0447x over previous
#include <cuda_runtime.h>
#include <cstdint>

// Problem constants
#define HW4     65536          // (512*512)/4 float4-groups per (b,c) plane
#define NGROUP  524288         // NPIX/4
#define NPIX    2097152
#define TPB     128
#define GPB     128            // groups per tile (== TPB, 1 group/thread)
#define NTILES  4096           // NGROUP / GPB
#define GRID    456            // 152 SMs x 3 resident blocks -> 27 tiles/SM, 0.2% imbalance
#define STAGES  2

#define SY_TILE_BYTES  (GPB * 36 * 4)     // 18432 B sigma_y per tile

__device__ float        g_psum[GRID];
__device__ float        g_pmax[GRID];
__device__ unsigned int g_count = 0;

__device__ __forceinline__ uint32_t smem_u32(const void* p) {
    uint32_t a;
    asm("{ .reg .u64 t; cvta.to.shared.u64 t, %1; cvt.u32.u64 %0, t; }" : "=r"(a) : "l"(p));
    return a;
}

__device__ __forceinline__ void tma_sigma(const float4* dst, const float* sy,
                                          unsigned tile, uint32_t mbar) {
    asm volatile("mbarrier.arrive.expect_tx.shared.b64 _, [%0], %1;"
                 :: "r"(mbar), "r"((uint32_t)SY_TILE_BYTES) : "memory");
    asm volatile(
        "cp.async.bulk.shared::cta.global.mbarrier::complete_tx::bytes "
        "[%0], [%1], %2, [%3];"
        :: "r"(smem_u32(dst)),
           "l"((const char*)sy + (size_t)tile * SY_TILE_BYTES),
           "r"((uint32_t)SY_TILE_BYTES), "r"(mbar) : "memory");
}

__device__ __forceinline__ void mbar_wait(uint32_t mbar, uint32_t parity) {
    uint32_t done;
    asm volatile(
        "{\n\t.reg .pred p;\n\t"
        "mbarrier.try_wait.parity.acquire.cta.shared::cta.b64 p, [%1], %2;\n\t"
        "selp.b32 %0, 1, 0, p;\n\t}"
        : "=r"(done) : "r"(mbar), "r"(parity) : "memory");
    while (!done) {
        asm volatile(
            "{\n\t.reg .pred p;\n\t"
            "mbarrier.try_wait.parity.acquire.cta.shared::cta.b64 p, [%1], %2, 0x989680;\n\t"
            "selp.b32 %0, 1, 0, p;\n\t}"
            : "=r"(done) : "r"(mbar), "r"(parity) : "memory");
    }
}

// load the 6 tg/mu float4s for a tile (issued early = software prefetch)
__device__ __forceinline__ void load_tm(const float4* __restrict__ tg,
                                        const float4* __restrict__ mu,
                                        unsigned tile, unsigned tid,
                                        float4& T0, float4& T1, float4& T2,
                                        float4& M0, float4& M1, float4& M2) {
    const unsigned g  = tile * GPB + tid;
    const unsigned b  = g >> 16;
    const unsigned tb = b * 3 * HW4 + (g & (HW4 - 1));
    T0 = tg[tb];           M0 = mu[tb];
    T1 = tg[tb + HW4];     M1 = mu[tb + HW4];
    T2 = tg[tb + 2 * HW4]; M2 = mu[tb + 2 * HW4];
}

__global__ __launch_bounds__(TPB, 4) void map_loss_fused(
    const float4* __restrict__ tg,
    const float4* __restrict__ mu,
    const float*  __restrict__ sy,
    float* __restrict__ out)
{
    __shared__ alignas(128) float4 s_sy[STAGES][GPB * 9];   // 2 x 18432 B
    __shared__ alignas(8)  uint64_t s_mbar[STAGES];

    const unsigned tid = threadIdx.x;
    const unsigned bid = blockIdx.x;
    const int ntile = (NTILES - (int)bid + GRID - 1) / GRID;   // 8 or 9

    if (tid == 0) {
        asm volatile("mbarrier.init.shared.b64 [%0], 1;" :: "r"(smem_u32(&s_mbar[0])) : "memory");
        asm volatile("mbarrier.init.shared.b64 [%0], 1;" :: "r"(smem_u32(&s_mbar[1])) : "memory");
    }
    __syncthreads();
    if (tid == 0) {
        tma_sigma(s_sy[0], sy, bid, smem_u32(&s_mbar[0]));
        if (ntile > 1)
            tma_sigma(s_sy[1], sy, bid + GRID, smem_u32(&s_mbar[1]));
    }

    // register prefetch of tg/mu for tile 0
    float4 cT0, cT1, cT2, cM0, cM1, cM2;
    load_tm(tg, mu, bid, tid, cT0, cT1, cT2, cM0, cM1, cM2);

    float lsum = 0.0f;
    float lmax = -3.0e38f;

    for (int k = 0; k < ntile; ++k) {
        const int      stage  = k & 1;
        const uint32_t parity = (k >> 1) & 1;

        // prefetch tg/mu for NEXT tile before blocking on this tile's sigma
        float4 nT0, nT1, nT2, nM0, nM1, nM2;
        if (k + 1 < ntile)
            load_tm(tg, mu, bid + (unsigned)(k + 1) * GRID, tid,
                    nT0, nT1, nT2, nM0, nM1, nM2);

        mbar_wait(smem_u32(&s_mbar[stage]), parity);

        // sigma -> registers, then free the buffer immediately
        float S[36];
        #pragma unroll
        for (int q = 0; q < 9; ++q) {
            const float4 v = s_sy[stage][tid * 9 + q];
            S[4 * q + 0] = v.x; S[4 * q + 1] = v.y;
            S[4 * q + 2] = v.z; S[4 * q + 3] = v.w;
        }
        __syncthreads();
        if (tid == 0 && k + STAGES < ntile)
            tma_sigma(s_sy[stage], sy, bid + (unsigned)(k + STAGES) * GRID,
                      smem_u32(&s_mbar[stage]));

        // ---- math ----
        const float r0[4] = {cT0.x - cM0.x, cT0.y - cM0.y, cT0.z - cM0.z, cT0.w - cM0.w};
        const float r1[4] = {cT1.x - cM1.x, cT1.y - cM1.y, cT1.z - cM1.z, cT1.w - cM1.w};
        const float r2[4] = {cT2.x - cM2.x, cT2.y - cM2.y, cT2.z - cM2.z, cT2.w - cM2.w};

        float quad[4], det[4];
        #pragma unroll
        for (int j = 0; j < 4; ++j) {
            const float a  = S[9 * j + 0];
            const float bb = S[9 * j + 1];
            const float c  = S[9 * j + 2];
            const float d  = S[9 * j + 4];
            const float e  = S[9 * j + 5];
            const float f  = S[9 * j + 8];
            const float A00 = d * f - e * e;
            const float A01 = c * e - bb * f;
            const float A02 = bb * e - c * d;
            const float A11 = a * f - c * c;
            const float A12 = bb * c - a * e;
            const float A22 = a * d - bb * bb;
            det[j] = a * A00 + bb * A01 + c * A02;
            quad[j] = r0[j] * r0[j] * A00 + r1[j] * r1[j] * A11 + r2[j] * r2[j] * A22
                    + 2.0f * (r0[j] * r1[j] * A01 + r0[j] * r2[j] * A02 + r1[j] * r2[j] * A12);
            // guard: t1 = 0.5*quad/det > 1e8  <=>  quad - 2e8*det > 0  (det > 0)
            lmax = fmaxf(lmax, quad[j] - 2.0e8f * det[j]);
        }

        const float d01 = det[0] * det[1];
        const float d23 = det[2] * det[3];
        const float num = (quad[0] * det[1] + quad[1] * det[0]) * d23
                        + (quad[2] * det[3] + quad[3] * det[2]) * d01;
        const float dp  = d01 * d23;            // dets >= 1, product <= ~1e13 : safe
        lsum += 0.5f * (__fdividef(num, dp) + __logf(dp));

        // rotate prefetched registers
        cT0 = nT0; cT1 = nT1; cT2 = nT2;
        cM0 = nM0; cM1 = nM1; cM2 = nM2;
    }

    // ---- intra-block reduction (4 warps) ----
    const int lane = tid & 31;
    const int wid  = tid >> 5;
    #pragma unroll
    for (int off = 16; off > 0; off >>= 1) {
        lsum += __shfl_down_sync(0xffffffffu, lsum, off);
        lmax  = fmaxf(lmax, __shfl_down_sync(0xffffffffu, lmax, off));
    }
    __shared__ float wsum[TPB / 32];
    __shared__ float wmax[TPB / 32];
    if (lane == 0) { wsum[wid] = lsum; wmax[wid] = lmax; }
    __syncthreads();
    __shared__ bool s_last;
    if (tid == 0) {
        float bs = wsum[0], bm = wmax[0];
        #pragma unroll
        for (int w = 1; w < TPB / 32; ++w) { bs += wsum[w]; bm = fmaxf(bm, wmax[w]); }
        g_psum[bid] = bs;
        g_pmax[bid] = bm;
        __threadfence();
        const unsigned done = atomicAdd(&g_count, 1u);
        s_last = (done == GRID - 1);
    }
    __syncthreads();

    // ---- last block finalizes (no second launch) — scalar gather (proven) ----
    if (s_last) {
        double ds = 0.0;
        float  dm = -3.0e38f;
        #pragma unroll
        for (int k = 0; k < (GRID + TPB - 1) / TPB; ++k) {
            const int idx = tid + k * TPB;
            if (idx < GRID) {
                ds += (double)g_psum[idx];
                dm  = fmaxf(dm, g_pmax[idx]);
            }
        }
        __shared__ double fsum[TPB];
        __shared__ float  fmaxv[TPB];
        fsum[tid]  = ds;
        fmaxv[tid] = dm;
        __syncthreads();
        #pragma unroll
        for (int off = TPB / 2; off > 0; off >>= 1) {
            if (tid < off) {
                fsum[tid] += fsum[tid + off];
                fmaxv[tid] = fmaxf(fmaxv[tid], fmaxv[tid + off]);
            }
            __syncthreads();
        }
        if (tid == 0) {
            float loss = (float)(fsum[0] / (double)NPIX);
            if (fmaxv[0] > 0.0f) loss = 0.0f;   // max(t1) > 1e8 guard
            out[0] = loss;
            g_count = 0;                         // reset for next graph replay
        }
    }
}

extern "C" void kernel_launch(void* const* d_in, const int* in_sizes, int n_in,
                              void* d_out, int out_size)
{
    // metadata order: target, mu, sigma_mu, sigma_n, sigma_y
    const float4* target = (const float4*)d_in[0];
    const float4* mu     = (const float4*)d_in[1];
    const float*  sy     = (const float*)d_in[4];
    float* out = (float*)d_out;

    map_loss_fused<<<GRID, TPB>>>(target, mu, sy, out);
}